// round 8
// baseline (speedup 1.0000x reference)
#include <cuda_runtime.h>
#include <cstdint>

// Problem sizes (fixed by the reference)
#define B_N 8
#define L_N 4096
#define F_N 64

#define TILE_M 256
#define KC 64                    // k floats per chunk = 256 B per adj row
#define NCHUNK (L_N / KC)        // 64
#define STAGES 3                 // per-warp A stages

// Per-warp A stage: 32 rows x 272 B pitch (256 data + 16 pad -> conflict-free LDS)
#define A_PITCH 272
#define A_WSLOT (32 * A_PITCH)               // 8704
#define WARP_AREA (STAGES * A_WSLOT)         // 26112
#define OFF_MBAR (8 * WARP_AREA)             // 208896
#define SMEM_BYTES (OFF_MBAR + 256)          // 209152

// hidden, packed for LDG.128 B-fragment loads:
// float offset = (kb*4 + j)*128 + group*16 + tig*4 + (nt&1)*2 + p   (+ b*512*512)
// where for element (b, l, o): kb=l>>3, kr=l&7, tig=kr&3, p=kr>>2,
//                              nt=o>>3, j=nt>>1, group=o&7
__device__ float g_hiddenP[(size_t)B_N * 512 * 512];

// ---------------------------------------------------------------------------
// helpers
// ---------------------------------------------------------------------------
__device__ __forceinline__ uint32_t smem_u32(const void* p) {
    uint32_t a;
    asm("{ .reg .u64 t; cvta.to.shared.u64 t, %1; cvt.u32.u64 %0, t; }" : "=r"(a) : "l"(p));
    return a;
}

__device__ __forceinline__ void bulk_cp(uint32_t dst, const void* src, uint32_t mbar) {
    asm volatile(
        "cp.async.bulk.shared::cta.global.mbarrier::complete_tx::bytes [%0], [%1], 256, [%2];"
        :: "r"(dst), "l"(src), "r"(mbar) : "memory");
}

__device__ __forceinline__ void mbar_expect(uint32_t mbar, uint32_t bytes) {
    asm volatile("mbarrier.arrive.expect_tx.shared.b64 _, [%0], %1;"
                 :: "r"(mbar), "r"(bytes) : "memory");
}

__device__ __forceinline__ void mbar_wait(uint32_t addr, uint32_t parity) {
    asm volatile(
        "{\n\t.reg .pred P;\n\t"
        "W_%=:\n\t"
        "mbarrier.try_wait.parity.acquire.cta.shared::cta.b64 P, [%0], %1, 0x989680;\n\t"
        "@!P bra W_%=;\n\t}"
        :: "r"(addr), "r"(parity) : "memory");
}

__device__ __forceinline__ void mma_tf32(float* c, uint32_t a0, uint32_t a1,
                                         uint32_t a2, uint32_t a3,
                                         uint32_t b0, uint32_t b1) {
    asm volatile(
        "mma.sync.aligned.m16n8k8.row.col.f32.tf32.tf32.f32 "
        "{%0,%1,%2,%3}, {%4,%5,%6,%7}, {%8,%9}, {%0,%1,%2,%3};"
        : "+f"(c[0]), "+f"(c[1]), "+f"(c[2]), "+f"(c[3])
        : "r"(a0), "r"(a1), "r"(a2), "r"(a3), "r"(b0), "r"(b1));
}

__device__ __forceinline__ float lds_f(const char* p) {
    return *reinterpret_cast<const float*>(p);
}

// ---------------------------------------------------------------------------
// Kernel A: hidden = text @ W, written tf32-rounded into LDG.128-packed layout
// ---------------------------------------------------------------------------
__global__ void __launch_bounds__(256) hidden_kernel(const float* __restrict__ text,
                                                     const float* __restrict__ weight) {
    __shared__ float s_text[64][65];
    __shared__ float s_w[64][64];
    const int b = blockIdx.y;
    const int l0 = blockIdx.x * 64;
    const int t = threadIdx.x;

    const float* tp = text + ((size_t)b * L_N + l0) * F_N;
#pragma unroll
    for (int j = 0; j < 16; j++) {
        int idx = j * 256 + t;  // 0..4095
        s_text[idx >> 6][idx & 63] = tp[idx];
        s_w[idx >> 6][idx & 63] = weight[idx];
    }
    __syncthreads();

    const int l = t & 63;
    const int og = t >> 6;  // 0..3 -> o = og*16 + i
    float acc[16];
#pragma unroll
    for (int i = 0; i < 16; i++) acc[i] = 0.0f;

    for (int f = 0; f < 64; f++) {
        float tv = s_text[l][f];
#pragma unroll
        for (int i = 0; i < 16; i++) acc[i] += tv * s_w[f][og * 16 + i];
    }

    const int lg = l0 + l;
    const int kb = lg >> 3;
    const int kr = lg & 7;
    const int tig = kr & 3;
    const int p = kr >> 2;
    float* dst = g_hiddenP + ((size_t)b * 512 + kb) * 512 + tig * 4 + p;
#pragma unroll
    for (int i = 0; i < 16; i++) {
        int o = og * 16 + i;
        int nt = o >> 3, j = nt >> 1, group = o & 7;
        uint32_t u;
        asm("cvt.rna.tf32.f32 %0, %1;" : "=r"(u) : "f"(acc[i]));
        dst[j * 128 + group * 16 + (nt & 1) * 2] = __uint_as_float(u);
    }
}

// ---------------------------------------------------------------------------
// Kernel B: out[b] = adj[b] @ hidden[b] + bias
// 256 threads (8 warps), 256x64 CTA tile, warp tile 32x64, mma.sync tf32.
// adj moved by cp.async.bulk (256 B/op) into per-warp 3-stage rings guarded
// by per-warp mbarriers. No CTA barriers in the mainloop.
// ---------------------------------------------------------------------------
__global__ void __launch_bounds__(256, 1) gemm_kernel(const float* __restrict__ adj,
                                                      const float* __restrict__ bias,
                                                      float* __restrict__ out) {
    extern __shared__ char smem[];
    const uint32_t sb = smem_u32(smem);

    const int t = threadIdx.x;
    const int w = t >> 5;         // 0..7
    const int lane = t & 31;
    const int group = lane >> 2;  // 0..7
    const int tig = lane & 3;     // 0..3
    const int b = blockIdx.y;
    const int m0 = blockIdx.x * TILE_M;

    // warp's private A rows: m0 + w*32 .. +31
    const float* aG = adj + ((size_t)b * L_N + m0 + w * 32) * L_N;
    // B fragment base for this lane
    const float* bF = g_hiddenP + (size_t)b * 512 * 512 + group * 16 + tig * 4;

    const uint32_t wbase = sb + w * WARP_AREA;
    char* wptr = smem + w * WARP_AREA;
    const uint32_t mb = sb + OFF_MBAR + w * (STAGES * 8);

    if (lane == 0) {
#pragma unroll
        for (int s = 0; s < STAGES; s++)
            asm volatile("mbarrier.init.shared.b64 [%0], 1;" :: "r"(mb + s * 8) : "memory");
    }
    __syncthreads();   // one-time: mbarrier init visible before any bulk_cp

    // ---- per-warp bulk-copy stage issue (lane 0 only) ----
    auto issueA = [&](int chunk, int slot) {
        if (lane == 0) {
            const uint32_t bar = mb + slot * 8;
            mbar_expect(bar, 32 * 256);
            uint32_t as = wbase + slot * A_WSLOT;
            const float* src = aG + chunk * KC;
#pragma unroll
            for (int row = 0; row < 32; row++)
                bulk_cp(as + row * A_PITCH, src + (size_t)row * L_N, bar);
        }
    };

    // B fragment load: k8-block index kb -> 4 float4 (j=0..3)
#define LOADB(dst, kb)                                                         \
    {                                                                          \
        const float* _p = bF + (size_t)(kb) * 512;                             \
        (dst)[0] = __ldg(reinterpret_cast<const float4*>(_p));                 \
        (dst)[1] = __ldg(reinterpret_cast<const float4*>(_p + 128));           \
        (dst)[2] = __ldg(reinterpret_cast<const float4*>(_p + 256));           \
        (dst)[3] = __ldg(reinterpret_cast<const float4*>(_p + 384));           \
    }

    float acc[2][8][4];
#pragma unroll
    for (int mt = 0; mt < 2; mt++)
#pragma unroll
        for (int nt = 0; nt < 8; nt++)
#pragma unroll
            for (int r = 0; r < 4; r++) acc[mt][nt][r] = 0.0f;

    issueA(0, 0);
    issueA(1, 1);
    issueA(2, 2);

    float4 bq0[4], bq1[4];
    LOADB(bq0, 0);

    for (int i = 0; i < NCHUNK; i++) {
        const int slot = i % STAGES;
        mbar_wait(mb + slot * 8, (uint32_t)((i / STAGES) & 1));

        const char* as = wptr + slot * A_WSLOT;
        const int nkb = (i + 1 < NCHUNK) ? (i + 1) * 8 : i * 8;

#pragma unroll
        for (int s = 0; s < 8; s++) {
            // prefetch the next k8-block's B fragments into the other buffer
            const int pkb = (s == 7) ? nkb : (i * 8 + s + 1);
            if (s & 1) { LOADB(bq0, pkb); }
            else       { LOADB(bq1, pkb); }
            const float4* cur = (s & 1) ? bq1 : bq0;

            // A fragments: pitch-272 rows, cols s*32 + tig*4 (+16)
            const int cA = s * 32 + tig * 4;
#pragma unroll
            for (int mt = 0; mt < 2; mt++) {
                const int r0 = mt * 16 + group;   // local row
                const char* rp = as + r0 * A_PITCH;
                uint32_t a0 = __float_as_uint(lds_f(rp + cA));
                uint32_t a2 = __float_as_uint(lds_f(rp + cA + 16));
                uint32_t a1 = __float_as_uint(lds_f(rp + 8 * A_PITCH + cA));
                uint32_t a3 = __float_as_uint(lds_f(rp + 8 * A_PITCH + cA + 16));
#pragma unroll
                for (int jj = 0; jj < 4; jj++) {
                    mma_tf32(acc[mt][2 * jj], a0, a1, a2, a3,
                             __float_as_uint(cur[jj].x), __float_as_uint(cur[jj].y));
                    mma_tf32(acc[mt][2 * jj + 1], a0, a1, a2, a3,
                             __float_as_uint(cur[jj].z), __float_as_uint(cur[jj].w));
                }
            }
        }

        if (i + STAGES < NCHUNK) issueA(i + STAGES, slot);
    }

    // ---- epilogue: + bias, direct STG ----
#pragma unroll
    for (int mt = 0; mt < 2; mt++) {
        const int r0 = m0 + w * 32 + mt * 16 + group;
        float* op0 = out + ((size_t)b * L_N + r0) * F_N;
        float* op1 = op0 + 8 * F_N;
#pragma unroll
        for (int jj = 0; jj < 4; jj++) {
#pragma unroll
            for (int h = 0; h < 2; h++) {
                const int nt = 2 * jj + h;
                const int col = nt * 8 + tig * 2;
                const float b0 = __ldg(&bias[col]);
                const float b1 = __ldg(&bias[col + 1]);
                float2 v0 = make_float2(acc[mt][nt][0] + b0, acc[mt][nt][1] + b1);
                float2 v1 = make_float2(acc[mt][nt][2] + b0, acc[mt][nt][3] + b1);
                *reinterpret_cast<float2*>(op0 + col) = v0;
                *reinterpret_cast<float2*>(op1 + col) = v1;
            }
        }
    }
}

// ---------------------------------------------------------------------------
// launch
// ---------------------------------------------------------------------------
extern "C" void kernel_launch(void* const* d_in, const int* in_sizes, int n_in,
                              void* d_out, int out_size) {
    const float* text = (const float*)d_in[0];   // [8,4096,64]
    const float* adj = (const float*)d_in[1];    // [8,4096,4096]
    const float* weight = (const float*)d_in[2]; // [64,64]
    const float* bias = (const float*)d_in[3];   // [64]
    float* out = (float*)d_out;                  // [8,4096,64]

    cudaFuncSetAttribute(gemm_kernel, cudaFuncAttributeMaxDynamicSharedMemorySize,
                         SMEM_BYTES);

    hidden_kernel<<<dim3(L_N / 64, B_N), 256>>>(text, weight);
    gemm_kernel<<<dim3(L_N / TILE_M, B_N), 256, SMEM_BYTES>>>(adj, bias, out);
}

// round 9
// speedup vs baseline: 1.4614x; 1.4614x over previous
#include <cuda_runtime.h>
#include <cstdint>

// Problem sizes (fixed by the reference)
#define B_N 8
#define L_N 4096
#define F_N 64

#define TILE_M 128
#define KC 64                    // k floats per chunk = 256 B contiguous per adj row
#define NCHUNK (L_N / KC)        // 64
#define STAGES 3

// A stage: 128 rows x 256 B, XOR-swizzled 16B chunks
#define A_STAGE 32768
#define SMEM_BYTES (STAGES * A_STAGE)   // 98304 -> 2 CTAs/SM

// hidden, packed for LDG.128 B-fragment loads:
// float offset = (kb*4 + j)*128 + group*16 + tig*4 + (nt&1)*2 + p   (+ b*512*512)
// where for element (b, l, o): kb=l>>3, kr=l&7, tig=kr&3, p=kr>>2,
//                              nt=o>>3, j=nt>>1, group=o&7
__device__ float g_hiddenP[(size_t)B_N * 512 * 512];

// ---------------------------------------------------------------------------
// helpers
// ---------------------------------------------------------------------------
__device__ __forceinline__ uint32_t smem_u32(const void* p) {
    uint32_t a;
    asm("{ .reg .u64 t; cvta.to.shared.u64 t, %1; cvt.u32.u64 %0, t; }" : "=r"(a) : "l"(p));
    return a;
}

__device__ __forceinline__ void cp16(uint32_t dst, const void* src) {
    asm volatile("cp.async.cg.shared.global [%0], [%1], 16;" :: "r"(dst), "l"(src) : "memory");
}

__device__ __forceinline__ void mma_tf32(float* c, uint32_t a0, uint32_t a1,
                                         uint32_t a2, uint32_t a3,
                                         uint32_t b0, uint32_t b1) {
    asm volatile(
        "mma.sync.aligned.m16n8k8.row.col.f32.tf32.tf32.f32 "
        "{%0,%1,%2,%3}, {%4,%5,%6,%7}, {%8,%9}, {%0,%1,%2,%3};"
        : "+f"(c[0]), "+f"(c[1]), "+f"(c[2]), "+f"(c[3])
        : "r"(a0), "r"(a1), "r"(a2), "r"(a3), "r"(b0), "r"(b1));
}

__device__ __forceinline__ float lds_f(const char* p) {
    return *reinterpret_cast<const float*>(p);
}

// ---------------------------------------------------------------------------
// Kernel A: hidden = text @ W, written tf32-rounded into LDG.128-packed layout
// ---------------------------------------------------------------------------
__global__ void __launch_bounds__(256) hidden_kernel(const float* __restrict__ text,
                                                     const float* __restrict__ weight) {
    __shared__ float s_text[64][65];
    __shared__ float s_w[64][64];
    const int b = blockIdx.y;
    const int l0 = blockIdx.x * 64;
    const int t = threadIdx.x;

    const float* tp = text + ((size_t)b * L_N + l0) * F_N;
#pragma unroll
    for (int j = 0; j < 16; j++) {
        int idx = j * 256 + t;  // 0..4095
        s_text[idx >> 6][idx & 63] = tp[idx];
        s_w[idx >> 6][idx & 63] = weight[idx];
    }
    __syncthreads();

    const int l = t & 63;
    const int og = t >> 6;  // 0..3 -> o = og*16 + i
    float acc[16];
#pragma unroll
    for (int i = 0; i < 16; i++) acc[i] = 0.0f;

    for (int f = 0; f < 64; f++) {
        float tv = s_text[l][f];
#pragma unroll
        for (int i = 0; i < 16; i++) acc[i] += tv * s_w[f][og * 16 + i];
    }

    const int lg = l0 + l;
    const int kb = lg >> 3;
    const int kr = lg & 7;
    const int tig = kr & 3;
    const int p = kr >> 2;
    float* dst = g_hiddenP + ((size_t)b * 512 + kb) * 512 + tig * 4 + p;
#pragma unroll
    for (int i = 0; i < 16; i++) {
        int o = og * 16 + i;
        int nt = o >> 3, j = nt >> 1, group = o & 7;
        uint32_t u;
        asm("cvt.rna.tf32.f32 %0, %1;" : "=r"(u) : "f"(acc[i]));
        dst[j * 128 + group * 16 + (nt & 1) * 2] = __uint_as_float(u);
    }
}

// ---------------------------------------------------------------------------
// Kernel B: out[b] = adj[b] @ hidden[b] + bias
// 128 threads (4 warps), 128x64 CTA tile, warp tile 32x64, mma.sync tf32.
// adj via cp.async, KC=64 -> 256B contiguous per row per chunk.
// 3 A-only stages (96KB) -> 2 CTAs/SM. B fragments via LDG.128 (L1 broadcast),
// register double-buffered. One __syncthreads per chunk.
// ---------------------------------------------------------------------------
__global__ void __launch_bounds__(128, 2) gemm_kernel(const float* __restrict__ adj,
                                                      const float* __restrict__ bias,
                                                      float* __restrict__ out) {
    extern __shared__ char smem[];
    const uint32_t sb = smem_u32(smem);

    const int t = threadIdx.x;
    const int w = t >> 5;         // 0..3
    const int lane = t & 31;
    const int group = lane >> 2;  // 0..7
    const int tig = lane & 3;     // 0..3
    const int b = blockIdx.y;
    const int m0 = blockIdx.x * TILE_M;

    const float* aG = adj + ((size_t)b * L_N + m0) * L_N;
    // B fragment base for this lane
    const float* bF = g_hiddenP + (size_t)b * 512 * 512 + group * 16 + tig * 4;

    // ---- CTA-wide cp.async stage issue: 128 rows x 256B, swizzled ----
    auto issueA = [&](int chunk, int slot) {
        uint32_t as = sb + slot * A_STAGE;
        const float* src = aG + chunk * KC;
#pragma unroll
        for (int j = 0; j < 16; j++) {
            int q = j * 128 + t;         // 0..2047
            int row = q >> 4, seg = q & 15;
            cp16(as + row * 256 + ((seg ^ (row & 7)) << 4),
                 src + (size_t)row * L_N + seg * 4);
        }
    };

    // B fragment load: k8-block index kb -> 4 float4 (j=0..3)
#define LOADB(dst, kb)                                                         \
    {                                                                          \
        const float* _p = bF + (size_t)(kb) * 512;                             \
        (dst)[0] = __ldg(reinterpret_cast<const float4*>(_p));                 \
        (dst)[1] = __ldg(reinterpret_cast<const float4*>(_p + 128));           \
        (dst)[2] = __ldg(reinterpret_cast<const float4*>(_p + 256));           \
        (dst)[3] = __ldg(reinterpret_cast<const float4*>(_p + 384));           \
    }

    float acc[2][8][4];
#pragma unroll
    for (int mt = 0; mt < 2; mt++)
#pragma unroll
        for (int nt = 0; nt < 8; nt++)
#pragma unroll
            for (int r = 0; r < 4; r++) acc[mt][nt][r] = 0.0f;

    issueA(0, 0);
    asm volatile("cp.async.commit_group;" ::: "memory");
    issueA(1, 1);
    asm volatile("cp.async.commit_group;" ::: "memory");

    float4 bq0[4], bq1[4];
    LOADB(bq0, 0);

    for (int i = 0; i < NCHUNK; i++) {
        asm volatile("cp.async.wait_group 1;" ::: "memory");
        __syncthreads();

        // issue i+2 into slot (i+2)%3 = (i-1)%3: chunk i-1's compute finished
        // before this CTA-wide sync, so the WAR on that slot is closed.
        if (i + 2 < NCHUNK) issueA(i + 2, (i + 2) % STAGES);
        asm volatile("cp.async.commit_group;" ::: "memory");

        const char* as = smem + (i % STAGES) * A_STAGE;

#pragma unroll
        for (int s = 0; s < 8; s++) {
            const int g = i * 8 + s;
            const int pkb = (g + 1 < 512) ? g + 1 : g;   // prefetch next k8-block
            if (s & 1) { LOADB(bq0, pkb); }
            else       { LOADB(bq1, pkb); }
            const float4* cur = (s & 1) ? bq1 : bq0;

            const int c0 = ((2 * s) ^ group) << 4;
            const int c1 = ((2 * s + 1) ^ group) << 4;
#pragma unroll
            for (int mt = 0; mt < 2; mt++) {
                const int r0 = w * 32 + mt * 16 + group;
                const char* rp = as + r0 * 256;
                uint32_t a0 = __float_as_uint(lds_f(rp + c0 + tig * 4));
                uint32_t a2 = __float_as_uint(lds_f(rp + c1 + tig * 4));
                uint32_t a1 = __float_as_uint(lds_f(rp + 8 * 256 + c0 + tig * 4));
                uint32_t a3 = __float_as_uint(lds_f(rp + 8 * 256 + c1 + tig * 4));
#pragma unroll
                for (int jj = 0; jj < 4; jj++) {
                    mma_tf32(acc[mt][2 * jj], a0, a1, a2, a3,
                             __float_as_uint(cur[jj].x), __float_as_uint(cur[jj].y));
                    mma_tf32(acc[mt][2 * jj + 1], a0, a1, a2, a3,
                             __float_as_uint(cur[jj].z), __float_as_uint(cur[jj].w));
                }
            }
        }
    }

    // ---- epilogue: + bias, direct STG ----
#pragma unroll
    for (int mt = 0; mt < 2; mt++) {
        const int r0 = m0 + w * 32 + mt * 16 + group;
        float* op0 = out + ((size_t)b * L_N + r0) * F_N;
        float* op1 = op0 + 8 * F_N;
#pragma unroll
        for (int jj = 0; jj < 4; jj++) {
#pragma unroll
            for (int h = 0; h < 2; h++) {
                const int nt = 2 * jj + h;
                const int col = nt * 8 + tig * 2;
                const float b0 = __ldg(&bias[col]);
                const float b1 = __ldg(&bias[col + 1]);
                float2 v0 = make_float2(acc[mt][nt][0] + b0, acc[mt][nt][1] + b1);
                float2 v1 = make_float2(acc[mt][nt][2] + b0, acc[mt][nt][3] + b1);
                *reinterpret_cast<float2*>(op0 + col) = v0;
                *reinterpret_cast<float2*>(op1 + col) = v1;
            }
        }
    }
}

// ---------------------------------------------------------------------------
// launch
// ---------------------------------------------------------------------------
extern "C" void kernel_launch(void* const* d_in, const int* in_sizes, int n_in,
                              void* d_out, int out_size) {
    const float* text = (const float*)d_in[0];   // [8,4096,64]
    const float* adj = (const float*)d_in[1];    // [8,4096,4096]
    const float* weight = (const float*)d_in[2]; // [64,64]
    const float* bias = (const float*)d_in[3];   // [64]
    float* out = (float*)d_out;                  // [8,4096,64]

    cudaFuncSetAttribute(gemm_kernel, cudaFuncAttributeMaxDynamicSharedMemorySize,
                         SMEM_BYTES);

    hidden_kernel<<<dim3(L_N / 64, B_N), 256>>>(text, weight);
    gemm_kernel<<<dim3(L_N / TILE_M, B_N), 128, SMEM_BYTES>>>(adj, bias, out);
}